// round 13
// baseline (speedup 1.0000x reference)
#include <cuda_runtime.h>
#include <cuda_fp16.h>
#include <mma.h>
#include <cstdint>

using namespace nvcuda;

#define MAX_NODES 100000
#define MAX_EDGES 1600000
#define D 128

// ---------------------------------------------------------------------------
// Scratch (__device__ globals: allocation-free rule)
// ---------------------------------------------------------------------------
__device__ __align__(16) __half g_xh[(size_t)MAX_NODES * D];  // fp16 mirror of x
__device__ __align__(16) __half g_Wh[128 * 256];              // [out-col][k] fp16
__device__ int g_count[MAX_NODES];
__device__ int g_rowptr[MAX_NODES + 1];
__device__ int g_cursor[MAX_NODES];
__device__ int g_csr_src[MAX_EDGES];
__device__ int g_is64;

#define SCAN_T 256
#define SCAN_B 128
#define SCAN_PER 4   // 128*256*4 = 131072 >= 100001
__device__ int g_blocksum[SCAN_B];

// ---------------------------------------------------------------------------
// Phase -1: detect edge_index dtype (int64 vs int32)
// ---------------------------------------------------------------------------
__global__ void detect_kernel(const int* __restrict__ ei32) {
    if (threadIdx.x == 0 && blockIdx.x == 0) {
        int nz = 0;
#pragma unroll 1
        for (int i = 0; i < 64; i++) nz |= ei32[2 * i + 1];
        g_is64 = (nz == 0) ? 1 : 0;
    }
}

__global__ void init_kernel(int N) {
    int i = blockIdx.x * blockDim.x + threadIdx.x;
    if (i < N) g_count[i] = 0;
}

// Phase 0a: fp32 x -> fp16 mirror g_xh[node][128] (8 elements per thread)
__global__ void xconv_kernel(const float* __restrict__ x, int N) {
    int t = blockIdx.x * blockDim.x + threadIdx.x;
    int total8 = N * (D / 8);
    if (t >= total8) return;
    const float4* p = reinterpret_cast<const float4*>(x) + t * 2;
    float4 a = __ldg(p), b = __ldg(p + 1);
    __half2 h0 = __floats2half2_rn(a.x, a.y);
    __half2 h1 = __floats2half2_rn(a.z, a.w);
    __half2 h2 = __floats2half2_rn(b.x, b.y);
    __half2 h3 = __floats2half2_rn(b.z, b.w);
    uint4 ov;
    ov.x = *reinterpret_cast<uint32_t*>(&h0);
    ov.y = *reinterpret_cast<uint32_t*>(&h1);
    ov.z = *reinterpret_cast<uint32_t*>(&h2);
    ov.w = *reinterpret_cast<uint32_t*>(&h3);
    reinterpret_cast<uint4*>(g_xh)[t] = ov;
}

// Phase 0b: preconvert W_cat to fp16, layout [o][k], k=0..255
__global__ void wconv_kernel(const float* __restrict__ Wl, const float* __restrict__ Wr) {
    int t = blockIdx.x * blockDim.x + threadIdx.x;
    if (t >= 128 * 256) return;
    int o = t >> 8, k = t & 255;
    float w = (k < 128) ? Wl[o * 128 + k] : Wr[o * 128 + (k - 128)];
    g_Wh[t] = __float2half_rn(w);
}

// Phase 1: degree histogram, 2 edges per thread, vector loads
__global__ void hist_kernel(const int* __restrict__ ei32, int E) {
    int e = (blockIdx.x * blockDim.x + threadIdx.x) * 2;
    if (e >= E) return;
    int d0, d1 = -1;
    if (g_is64) {
        int4 v = *reinterpret_cast<const int4*>(ei32 + 2 * (E + e));  // 2 longs
        d0 = v.x;
        if (e + 1 < E) d1 = v.z;
    } else {
        int2 v = *reinterpret_cast<const int2*>(ei32 + E + e);
        d0 = v.x;
        if (e + 1 < E) d1 = v.y;
    }
    atomicAdd(&g_count[d0], 1);
    if (d1 >= 0) atomicAdd(&g_count[d1], 1);
}

// ---------------------------------------------------------------------------
// Phase 2: exclusive scan of g_count -> g_rowptr (3 kernels)
// ---------------------------------------------------------------------------
__global__ __launch_bounds__(SCAN_T) void scan1_kernel(int N) {
    __shared__ int sh[SCAN_T];
    int t = threadIdx.x, b = blockIdx.x;
    int base = (b * SCAN_T + t) * SCAN_PER;
    int v[SCAN_PER];
    int s = 0;
#pragma unroll
    for (int i = 0; i < SCAN_PER; i++) {
        v[i] = (base + i < N) ? g_count[base + i] : 0;
        s += v[i];
    }
    sh[t] = s;
    __syncthreads();
    for (int off = 1; off < SCAN_T; off <<= 1) {
        int xv = (t >= off) ? sh[t - off] : 0;
        __syncthreads();
        sh[t] += xv;
        __syncthreads();
    }
    int run = sh[t] - s;
#pragma unroll
    for (int i = 0; i < SCAN_PER; i++) {
        if (base + i < N) g_rowptr[base + i] = run;
        run += v[i];
    }
    if (t == SCAN_T - 1) g_blocksum[b] = sh[t];
}

__global__ __launch_bounds__(SCAN_B) void scan2_kernel() {
    __shared__ int sh[SCAN_B];
    int t = threadIdx.x;
    int orig = g_blocksum[t];
    sh[t] = orig;
    __syncthreads();
    for (int off = 1; off < SCAN_B; off <<= 1) {
        int xv = (t >= off) ? sh[t - off] : 0;
        __syncthreads();
        sh[t] += xv;
        __syncthreads();
    }
    g_blocksum[t] = sh[t] - orig;
}

__global__ __launch_bounds__(SCAN_T) void scan3_kernel(int N, int E) {
    int t = threadIdx.x, b = blockIdx.x;
    int off = g_blocksum[b];
    int base = (b * SCAN_T + t) * SCAN_PER;
#pragma unroll
    for (int i = 0; i < SCAN_PER; i++) {
        int idx = base + i;
        if (idx < N) {
            int r = g_rowptr[idx] + off;
            g_rowptr[idx] = r;
            g_cursor[idx] = r;
        }
    }
    if (b == 0 && t == 0) g_rowptr[N] = E;
}

// Phase 3: fill CSR src lists, 2 edges per thread, vector loads
__global__ void fill_kernel(const int* __restrict__ ei32, int E) {
    int e = (blockIdx.x * blockDim.x + threadIdx.x) * 2;
    if (e >= E) return;
    int s0, d0, s1 = -1, d1 = -1;
    if (g_is64) {
        int4 sv = *reinterpret_cast<const int4*>(ei32 + 2 * e);
        int4 dv = *reinterpret_cast<const int4*>(ei32 + 2 * (E + e));
        s0 = sv.x; d0 = dv.x;
        if (e + 1 < E) { s1 = sv.z; d1 = dv.z; }
    } else {
        int2 sv = *reinterpret_cast<const int2*>(ei32 + e);
        int2 dv = *reinterpret_cast<const int2*>(ei32 + E + e);
        s0 = sv.x; d0 = dv.x;
        if (e + 1 < E) { s1 = sv.y; d1 = dv.y; }
    }
    int p0 = atomicAdd(&g_cursor[d0], 1);
    g_csr_src[p0] = s0;
    if (d1 >= 0) {
        int p1 = atomicAdd(&g_cursor[d1], 1);
        g_csr_src[p1] = s1;
    }
}

// ---------------------------------------------------------------------------
// Phase 4+5 FUSED: gather-mean into smem, then fp16 WMMA GEMM.
//   out[128n x 128o] = [mean | x][128 x 256] * Wcat^T + bias  (fp32 accum)
// Gather: 8 warps x 16 nodes each; lane owns 4 halves (uint2); fp32 accum,
//         fp16 mean written to resident smem tile mean_s (stride 136 halves).
// GEMM:   K chunks of 32. Chunks 0..3: A frags straight from mean_s.
//         Chunks 4..7: stage x from g_xh into ax_s (stride 40). W staged
//         every chunk into w_s (stride 40). Bias tile aliases ax_s
//         (consumed into accumulators before the K-loop).
// ---------------------------------------------------------------------------
#define ASTR 40
#define MSTR 136
#define SM_MEAN_HALVES (128 * MSTR)            // 34816 B
#define SM_W_HALVES    (128 * ASTR)            // 10240 B
#define SM_AX_HALVES   (128 * ASTR)            // 10240 B
#define SM_TOTAL_BYTES ((SM_MEAN_HALVES + SM_W_HALVES + SM_AX_HALVES) * 2)

__global__ __launch_bounds__(256) void fused_kernel(
    const float* __restrict__ bl,
    float* __restrict__ out,
    int N) {
    extern __shared__ __align__(16) __half smem[];
    __half* mean_s = smem;                       // [128][MSTR]
    __half* w_s    = smem + SM_MEAN_HALVES;      // [128][ASTR]
    __half* ax_s   = w_s + SM_W_HALVES;          // [128][ASTR]
    float*  bias_s = reinterpret_cast<float*>(ax_s);  // aliased, pre-loop only

    const int tid = threadIdx.x;
    const int wid = tid >> 5;
    const int lane = tid & 31;
    const int node0 = blockIdx.x * 128;
    const int wr = (wid & 3) * 32;   // warp row offset
    const int wc = (wid >> 2) * 64;  // warp col offset

    // ---- bias tile: 16 identical rows of bl[0..127] (aliased region) ----
    {
        float bv = __ldg(bl + (tid & 127));
        int r0 = tid >> 7;
#pragma unroll
        for (int r = 0; r < 16; r += 2)
            bias_s[(r + r0) * 128 + (tid & 127)] = bv;
    }

    // ---- gather phase: each warp computes means for 16 node rows ----
#pragma unroll 1
    for (int rr = 0; rr < 16; rr++) {
        int row = wid * 16 + rr;
        int gn = node0 + row;
        float4 acc = make_float4(0.f, 0.f, 0.f, 0.f);
        int deg = 0;
        if (gn < N) {
            int beg = g_rowptr[gn];
            int end = g_rowptr[gn + 1];
            deg = end - beg;
            int e = beg;
            for (; e + 3 < end; e += 4) {
                int s0 = g_csr_src[e];
                int s1 = g_csr_src[e + 1];
                int s2 = g_csr_src[e + 2];
                int s3 = g_csr_src[e + 3];
                uint2 a = __ldg(reinterpret_cast<const uint2*>(g_xh + (size_t)s0 * D) + lane);
                uint2 b = __ldg(reinterpret_cast<const uint2*>(g_xh + (size_t)s1 * D) + lane);
                uint2 c = __ldg(reinterpret_cast<const uint2*>(g_xh + (size_t)s2 * D) + lane);
                uint2 d = __ldg(reinterpret_cast<const uint2*>(g_xh + (size_t)s3 * D) + lane);
#pragma unroll
                for (int q = 0; q < 4; q++) {
                    uint2 v = (q == 0) ? a : (q == 1) ? b : (q == 2) ? c : d;
                    float2 f0 = __half22float2(*reinterpret_cast<__half2*>(&v.x));
                    float2 f1 = __half22float2(*reinterpret_cast<__half2*>(&v.y));
                    acc.x += f0.x; acc.y += f0.y; acc.z += f1.x; acc.w += f1.y;
                }
            }
            for (; e < end; e++) {
                int s = g_csr_src[e];
                uint2 v = __ldg(reinterpret_cast<const uint2*>(g_xh + (size_t)s * D) + lane);
                float2 f0 = __half22float2(*reinterpret_cast<__half2*>(&v.x));
                float2 f1 = __half22float2(*reinterpret_cast<__half2*>(&v.y));
                acc.x += f0.x; acc.y += f0.y; acc.z += f1.x; acc.w += f1.y;
            }
        }
        float inv = 1.0f / fmaxf((float)deg, 1.0f);
        __half2 m0 = __floats2half2_rn(acc.x * inv, acc.y * inv);
        __half2 m1 = __floats2half2_rn(acc.z * inv, acc.w * inv);
        uint2 o;
        o.x = *reinterpret_cast<uint32_t*>(&m0);
        o.y = *reinterpret_cast<uint32_t*>(&m1);
        *reinterpret_cast<uint2*>(&mean_s[row * MSTR + lane * 4]) = o;
    }
    __syncthreads();

    // ---- load bias into accumulators (consumes aliased ax_s region) ----
    wmma::fragment<wmma::accumulator, 16, 16, 16, float> acc[2][4];
#pragma unroll
    for (int i = 0; i < 2; i++)
#pragma unroll
        for (int j = 0; j < 4; j++)
            wmma::load_matrix_sync(acc[i][j], &bias_s[wc + j * 16], 128, wmma::mem_row_major);
    __syncthreads();   // bias consumed; ax_s free for staging

    const int row = tid >> 1;         // 0..127 (node row AND W out-col)
    const int seg = (tid & 1) * 16;   // 16-half segment of the 32-col chunk
    const int gn  = node0 + row;
    const bool va = (gn < N);

#pragma unroll 1
    for (int c = 0; c < 8; c++) {
        if (c > 0) __syncthreads();   // previous compute done; w_s/ax_s free
        // ---- stage x chunk (only for c >= 4) ----
        if (c >= 4) {
            uint4 v0, v1;
            if (va) {
                const uint4* p = reinterpret_cast<const uint4*>(g_xh + (size_t)gn * D + (c - 4) * 32 + seg);
                v0 = __ldg(p); v1 = __ldg(p + 1);
            } else {
                v0 = v1 = make_uint4(0, 0, 0, 0);
            }
            uint4* dst = reinterpret_cast<uint4*>(&ax_s[row * ASTR + seg]);
            dst[0] = v0; dst[1] = v1;
        }
        // ---- stage W chunk ----
        {
            const uint4* p = reinterpret_cast<const uint4*>(g_Wh + row * 256 + c * 32 + seg);
            uint4* dst = reinterpret_cast<uint4*>(&w_s[row * ASTR + seg]);
            dst[0] = __ldg(p); dst[1] = __ldg(p + 1);
        }
        __syncthreads();

        // ---- compute: 2 k-steps x 2 row frags x 4 col frags ----
        const __half* abase = (c < 4) ? (mean_s + c * 32) : ax_s;
        const unsigned lda  = (c < 4) ? MSTR : ASTR;
#pragma unroll
        for (int ks = 0; ks < 2; ks++) {
            wmma::fragment<wmma::matrix_a, 16, 16, 16, __half, wmma::row_major> af[2];
            wmma::fragment<wmma::matrix_b, 16, 16, 16, __half, wmma::col_major> bf[4];
#pragma unroll
            for (int i = 0; i < 2; i++)
                wmma::load_matrix_sync(af[i], abase + (wr + i * 16) * lda + ks * 16, lda);
#pragma unroll
            for (int j = 0; j < 4; j++)
                wmma::load_matrix_sync(bf[j], &w_s[(wc + j * 16) * ASTR + ks * 16], ASTR);
#pragma unroll
            for (int i = 0; i < 2; i++)
#pragma unroll
                for (int j = 0; j < 4; j++)
                    wmma::mma_sync(acc[i][j], af[i], bf[j], acc[i][j]);
        }
    }

    // ---- epilogue: direct fragment stores (bias already in acc) ----
#pragma unroll
    for (int i = 0; i < 2; i++) {
        int r0 = node0 + wr + i * 16;
        if (r0 < N) {  // N % 16 == 0 -> frag fully valid
#pragma unroll
            for (int j = 0; j < 4; j++)
                wmma::store_matrix_sync(out + (size_t)r0 * D + wc + j * 16, acc[i][j], D, wmma::mem_row_major);
        }
    }
}

// ---------------------------------------------------------------------------
extern "C" void kernel_launch(void* const* d_in, const int* in_sizes, int n_in,
                              void* d_out, int out_size) {
    const float* x    = (const float*)d_in[0];
    const int*   ei32 = (const int*)d_in[1];
    const float* Wl   = (const float*)d_in[2];
    const float* bl   = (const float*)d_in[3];
    const float* Wr   = (const float*)d_in[4];
    float*       out  = (float*)d_out;

    int N = in_sizes[0] / D;       // 100000
    int E = in_sizes[1] / 2;       // 1600000

    cudaFuncSetAttribute(fused_kernel, cudaFuncAttributeMaxDynamicSharedMemorySize, SM_TOTAL_BYTES);

    detect_kernel<<<1, 32>>>(ei32);
    init_kernel<<<(N + 255) / 256, 256>>>(N);
    xconv_kernel<<<(N * (D / 8) + 255) / 256, 256>>>(x, N);
    hist_kernel<<<(E / 2 + 255) / 256, 256>>>(ei32, E);
    wconv_kernel<<<(128 * 256 + 255) / 256, 256>>>(Wl, Wr);
    scan1_kernel<<<SCAN_B, SCAN_T>>>(N);
    scan2_kernel<<<1, SCAN_B>>>();
    scan3_kernel<<<SCAN_B, SCAN_T>>>(N, E);
    fill_kernel<<<(E / 2 + 255) / 256, 256>>>(ei32, E);
    fused_kernel<<<(N + 127) / 128, 256, SM_TOTAL_BYTES>>>(bl, out, N);
}

// round 15
// speedup vs baseline: 1.4063x; 1.4063x over previous
#include <cuda_runtime.h>
#include <cuda_fp16.h>
#include <mma.h>
#include <cstdint>

using namespace nvcuda;

#define MAX_NODES 100000
#define MAX_EDGES 1600000
#define D 128

// ---------------------------------------------------------------------------
// Scratch (__device__ globals: allocation-free rule)
// A_cat[node][256] fp16: cols 0..127 = mean agg, cols 128..255 = x row.
// ---------------------------------------------------------------------------
__device__ __align__(16) __half g_Acat[(size_t)MAX_NODES * 256];
__device__ __align__(16) __half g_Wh[128 * 256];   // [out-col][k] fp16
__device__ int g_count[MAX_NODES];
__device__ int g_rowptr[MAX_NODES + 1];
__device__ int g_cursor[MAX_NODES];
__device__ int g_csr_src[MAX_EDGES];
__device__ int g_is64;

#define SCAN_T 256
#define SCAN_B 128
#define SCAN_PER 4   // 128*256*4 = 131072 >= 100001
__device__ int g_blocksum[SCAN_B];

// ---------------------------------------------------------------------------
// Phase 0 (merged setup): detect dtype + zero counters + xconv + wconv.
// Grid partitioned by blockIdx:
//   [0, XB)            : xconv  (N*16 threads, 8 elems each)
//   [XB, XB+WB)        : wconv  (128*256 elems)
//   [XB+WB, XB+WB+IB)  : init   (N counters)
//   last block         : detect
// ---------------------------------------------------------------------------
#define XB ((MAX_NODES * 16 + 255) / 256)          // 6250
#define WB ((128 * 256 + 255) / 256)               // 128
#define IB ((MAX_NODES + 255) / 256)               // 391
#define SETUP_BLOCKS (XB + WB + IB + 1)

__global__ void setup_kernel(const float* __restrict__ x,
                             const float* __restrict__ Wl,
                             const float* __restrict__ Wr,
                             const int* __restrict__ ei32,
                             int N) {
    int b = blockIdx.x;
    if (b < XB) {
        int t = b * 256 + threadIdx.x;            // one per 8 elems
        int total8 = N * (D / 8);
        if (t >= total8) return;
        int node = t >> 4;
        int g = t & 15;
        const float4* p = reinterpret_cast<const float4*>(x + (size_t)node * D + g * 8);
        float4 a = __ldg(p), bb = __ldg(p + 1);
        __half2 h0 = __floats2half2_rn(a.x, a.y);
        __half2 h1 = __floats2half2_rn(a.z, a.w);
        __half2 h2 = __floats2half2_rn(bb.x, bb.y);
        __half2 h3 = __floats2half2_rn(bb.z, bb.w);
        uint4 ov;
        ov.x = *reinterpret_cast<uint32_t*>(&h0);
        ov.y = *reinterpret_cast<uint32_t*>(&h1);
        ov.z = *reinterpret_cast<uint32_t*>(&h2);
        ov.w = *reinterpret_cast<uint32_t*>(&h3);
        *reinterpret_cast<uint4*>(g_Acat + (size_t)node * 256 + 128 + g * 8) = ov;
    } else if (b < XB + WB) {
        int t = (b - XB) * 256 + threadIdx.x;
        if (t >= 128 * 256) return;
        int o = t >> 8, k = t & 255;
        float w = (k < 128) ? Wl[o * 128 + k] : Wr[o * 128 + (k - 128)];
        g_Wh[t] = __float2half_rn(w);
    } else if (b < XB + WB + IB) {
        int t = (b - XB - WB) * 256 + threadIdx.x;
        if (t < N) g_count[t] = 0;
    } else {
        if (threadIdx.x == 0) {
            int nz = 0;
#pragma unroll 1
            for (int i = 0; i < 64; i++) nz |= ei32[2 * i + 1];
            g_is64 = (nz == 0) ? 1 : 0;
        }
    }
}

// Phase 1: degree histogram, 4 edges per thread (2x int4 loads)
__global__ void hist_kernel(const int* __restrict__ ei32, int E) {
    int e = (blockIdx.x * blockDim.x + threadIdx.x) * 4;
    if (e >= E) return;
    int d[4];
    int n = (E - e < 4) ? (E - e) : 4;
    if (g_is64) {
        const int4* p = reinterpret_cast<const int4*>(ei32 + 2 * (E + e));
        int4 v0 = __ldg(p);
        d[0] = v0.x; d[1] = v0.z;
        if (n > 2) {
            int4 v1 = __ldg(p + 1);
            d[2] = v1.x; d[3] = v1.z;
        }
    } else {
        const int4* p = reinterpret_cast<const int4*>(ei32 + E + e);
        int4 v = __ldg(p);
        d[0] = v.x; d[1] = v.y; d[2] = v.z; d[3] = v.w;
    }
#pragma unroll
    for (int i = 0; i < 4; i++)
        if (i < n) atomicAdd(&g_count[d[i]], 1);
}

// ---------------------------------------------------------------------------
// Phase 2: exclusive scan of g_count -> g_rowptr (3 kernels)
// ---------------------------------------------------------------------------
__global__ __launch_bounds__(SCAN_T) void scan1_kernel(int N) {
    __shared__ int sh[SCAN_T];
    int t = threadIdx.x, b = blockIdx.x;
    int base = (b * SCAN_T + t) * SCAN_PER;
    int v[SCAN_PER];
    int s = 0;
#pragma unroll
    for (int i = 0; i < SCAN_PER; i++) {
        v[i] = (base + i < N) ? g_count[base + i] : 0;
        s += v[i];
    }
    sh[t] = s;
    __syncthreads();
    for (int off = 1; off < SCAN_T; off <<= 1) {
        int xv = (t >= off) ? sh[t - off] : 0;
        __syncthreads();
        sh[t] += xv;
        __syncthreads();
    }
    int run = sh[t] - s;
#pragma unroll
    for (int i = 0; i < SCAN_PER; i++) {
        if (base + i < N) g_rowptr[base + i] = run;
        run += v[i];
    }
    if (t == SCAN_T - 1) g_blocksum[b] = sh[t];
}

__global__ __launch_bounds__(SCAN_B) void scan2_kernel() {
    __shared__ int sh[SCAN_B];
    int t = threadIdx.x;
    int orig = g_blocksum[t];
    sh[t] = orig;
    __syncthreads();
    for (int off = 1; off < SCAN_B; off <<= 1) {
        int xv = (t >= off) ? sh[t - off] : 0;
        __syncthreads();
        sh[t] += xv;
        __syncthreads();
    }
    g_blocksum[t] = sh[t] - orig;
}

__global__ __launch_bounds__(SCAN_T) void scan3_kernel(int N, int E) {
    int t = threadIdx.x, b = blockIdx.x;
    int off = g_blocksum[b];
    int base = (b * SCAN_T + t) * SCAN_PER;
#pragma unroll
    for (int i = 0; i < SCAN_PER; i++) {
        int idx = base + i;
        if (idx < N) {
            int r = g_rowptr[idx] + off;
            g_rowptr[idx] = r;
            g_cursor[idx] = r;
        }
    }
    if (b == 0 && t == 0) g_rowptr[N] = E;
}

// Phase 3: fill CSR src lists, 4 edges per thread (int4 loads)
__global__ void fill_kernel(const int* __restrict__ ei32, int E) {
    int e = (blockIdx.x * blockDim.x + threadIdx.x) * 4;
    if (e >= E) return;
    int s[4], d[4];
    int n = (E - e < 4) ? (E - e) : 4;
    if (g_is64) {
        const int4* sp = reinterpret_cast<const int4*>(ei32 + 2 * e);
        const int4* dp = reinterpret_cast<const int4*>(ei32 + 2 * (E + e));
        int4 sv0 = __ldg(sp), dv0 = __ldg(dp);
        s[0] = sv0.x; s[1] = sv0.z; d[0] = dv0.x; d[1] = dv0.z;
        if (n > 2) {
            int4 sv1 = __ldg(sp + 1), dv1 = __ldg(dp + 1);
            s[2] = sv1.x; s[3] = sv1.z; d[2] = dv1.x; d[3] = dv1.z;
        }
    } else {
        int4 sv = __ldg(reinterpret_cast<const int4*>(ei32 + e));
        int4 dv = __ldg(reinterpret_cast<const int4*>(ei32 + E + e));
        s[0] = sv.x; s[1] = sv.y; s[2] = sv.z; s[3] = sv.w;
        d[0] = dv.x; d[1] = dv.y; d[2] = dv.z; d[3] = dv.w;
    }
#pragma unroll
    for (int i = 0; i < 4; i++) {
        if (i < n) {
            int pos = atomicAdd(&g_cursor[d[i]], 1);
            g_csr_src[pos] = s[i];
        }
    }
}

// ---------------------------------------------------------------------------
// Phase 4: gather-aggregate (mean) over fp16 x (A_cat cols 128..255).
// One warp per dst node; lane owns 4 halves (uint2 = 8B).
// fp32 accumulation; fp16 mean written to A_cat cols 0..127.
// ---------------------------------------------------------------------------
__global__ __launch_bounds__(256) void agg_kernel(int N) {
    int w = (blockIdx.x * blockDim.x + threadIdx.x) >> 5;
    int lane = threadIdx.x & 31;
    if (w >= N) return;
    int beg = g_rowptr[w];
    int end = g_rowptr[w + 1];
    float4 acc = make_float4(0.f, 0.f, 0.f, 0.f);
    int e = beg;
    for (; e + 3 < end; e += 4) {
        int s0 = g_csr_src[e];
        int s1 = g_csr_src[e + 1];
        int s2 = g_csr_src[e + 2];
        int s3 = g_csr_src[e + 3];
        uint2 a = __ldg(reinterpret_cast<const uint2*>(g_Acat + (size_t)s0 * 256 + 128) + lane);
        uint2 b = __ldg(reinterpret_cast<const uint2*>(g_Acat + (size_t)s1 * 256 + 128) + lane);
        uint2 c = __ldg(reinterpret_cast<const uint2*>(g_Acat + (size_t)s2 * 256 + 128) + lane);
        uint2 d = __ldg(reinterpret_cast<const uint2*>(g_Acat + (size_t)s3 * 256 + 128) + lane);
#pragma unroll
        for (int q = 0; q < 4; q++) {
            uint2 v = (q == 0) ? a : (q == 1) ? b : (q == 2) ? c : d;
            float2 f0 = __half22float2(*reinterpret_cast<__half2*>(&v.x));
            float2 f1 = __half22float2(*reinterpret_cast<__half2*>(&v.y));
            acc.x += f0.x; acc.y += f0.y; acc.z += f1.x; acc.w += f1.y;
        }
    }
    for (; e < end; e++) {
        int s = g_csr_src[e];
        uint2 v = __ldg(reinterpret_cast<const uint2*>(g_Acat + (size_t)s * 256 + 128) + lane);
        float2 f0 = __half22float2(*reinterpret_cast<__half2*>(&v.x));
        float2 f1 = __half22float2(*reinterpret_cast<__half2*>(&v.y));
        acc.x += f0.x; acc.y += f0.y; acc.z += f1.x; acc.w += f1.y;
    }
    float inv = 1.0f / fmaxf((float)(end - beg), 1.0f);
    __half2 m0 = __floats2half2_rn(acc.x * inv, acc.y * inv);
    __half2 m1 = __floats2half2_rn(acc.z * inv, acc.w * inv);
    uint2 o;
    o.x = *reinterpret_cast<uint32_t*>(&m0);
    o.y = *reinterpret_cast<uint32_t*>(&m1);
    *(reinterpret_cast<uint2*>(g_Acat + (size_t)w * 256) + lane) = o;
}

// ---------------------------------------------------------------------------
// Phase 5: single-pass fp16 WMMA GEMM.
//   out[128n x 128o] = Acat[128 x 256] * Wcat^T + bias  (fp32 accum)
// CTA 128x128, 256 threads = 8 warps, warp tile 32x64 (2x4 frags).
// K chunks of 32, smem stride 40 halves. Pure uint4 staging.
// ---------------------------------------------------------------------------
#define ASTR 40

__global__ __launch_bounds__(256, 2) void gemm_fp16_kernel(
    const float* __restrict__ bl,
    float* __restrict__ out,
    int N) {
    __shared__ __align__(16) __half a_s[128 * ASTR];
    __shared__ __align__(16) __half w_s[128 * ASTR];
    __shared__ __align__(16) float bias_s[16 * 128];

    const int tid = threadIdx.x;
    const int wid = tid >> 5;
    const int node0 = blockIdx.x * 128;
    const int wr = (wid & 3) * 32;   // warp row offset
    const int wc = (wid >> 2) * 64;  // warp col offset

    // bias tile: 16 identical rows of bl[0..127]
    {
        float bv = __ldg(bl + (tid & 127));
        int r0 = tid >> 7;
#pragma unroll
        for (int r = 0; r < 16; r += 2)
            bias_s[(r + r0) * 128 + (tid & 127)] = bv;
    }
    __syncthreads();

    wmma::fragment<wmma::accumulator, 16, 16, 16, float> acc[2][4];
#pragma unroll
    for (int i = 0; i < 2; i++)
#pragma unroll
        for (int j = 0; j < 4; j++)
            wmma::load_matrix_sync(acc[i][j], &bias_s[wc + j * 16], 128, wmma::mem_row_major);

    const int row = tid >> 1;         // 0..127 (node row AND W out-col)
    const int seg = (tid & 1) * 16;   // 16-half segment of the 32-col chunk
    const int gn  = node0 + row;
    const bool va = (gn < N);

#pragma unroll 1
    for (int c = 0; c < 8; c++) {
        __syncthreads();
        // ---- stage A chunk: pure fp16 uint4 copies ----
        {
            uint4 v0, v1;
            if (va) {
                const uint4* p = reinterpret_cast<const uint4*>(g_Acat + (size_t)gn * 256 + c * 32 + seg);
                v0 = __ldg(p); v1 = __ldg(p + 1);
            } else {
                v0 = v1 = make_uint4(0, 0, 0, 0);
            }
            uint4* dst = reinterpret_cast<uint4*>(&a_s[row * ASTR + seg]);
            dst[0] = v0; dst[1] = v1;
        }
        // ---- stage W chunk ----
        {
            const uint4* p = reinterpret_cast<const uint4*>(g_Wh + row * 256 + c * 32 + seg);
            uint4* dst = reinterpret_cast<uint4*>(&w_s[row * ASTR + seg]);
            dst[0] = __ldg(p); dst[1] = __ldg(p + 1);
        }
        __syncthreads();

        // ---- compute: 2 k-steps x 2 row frags x 4 col frags ----
#pragma unroll
        for (int ks = 0; ks < 2; ks++) {
            wmma::fragment<wmma::matrix_a, 16, 16, 16, __half, wmma::row_major> af[2];
            wmma::fragment<wmma::matrix_b, 16, 16, 16, __half, wmma::col_major> bf[4];
#pragma unroll
            for (int i = 0; i < 2; i++)
                wmma::load_matrix_sync(af[i], &a_s[(wr + i * 16) * ASTR + ks * 16], ASTR);
#pragma unroll
            for (int j = 0; j < 4; j++)
                wmma::load_matrix_sync(bf[j], &w_s[(wc + j * 16) * ASTR + ks * 16], ASTR);
#pragma unroll
            for (int i = 0; i < 2; i++)
#pragma unroll
                for (int j = 0; j < 4; j++)
                    wmma::mma_sync(acc[i][j], af[i], bf[j], acc[i][j]);
        }
    }

    // ---- epilogue: direct fragment stores (bias already in acc) ----
#pragma unroll
    for (int i = 0; i < 2; i++) {
        int r0 = node0 + wr + i * 16;
        if (r0 < N) {  // N % 16 == 0 -> frag fully valid
#pragma unroll
            for (int j = 0; j < 4; j++)
                wmma::store_matrix_sync(out + (size_t)r0 * D + wc + j * 16, acc[i][j], D, wmma::mem_row_major);
        }
    }
}

// ---------------------------------------------------------------------------
extern "C" void kernel_launch(void* const* d_in, const int* in_sizes, int n_in,
                              void* d_out, int out_size) {
    const float* x    = (const float*)d_in[0];
    const int*   ei32 = (const int*)d_in[1];
    const float* Wl   = (const float*)d_in[2];
    const float* bl   = (const float*)d_in[3];
    const float* Wr   = (const float*)d_in[4];
    float*       out  = (float*)d_out;

    int N = in_sizes[0] / D;       // 100000
    int E = in_sizes[1] / 2;       // 1600000

    setup_kernel<<<SETUP_BLOCKS, 256>>>(x, Wl, Wr, ei32, N);
    hist_kernel<<<(E / 4 + 255) / 256, 256>>>(ei32, E);
    scan1_kernel<<<SCAN_B, SCAN_T>>>(N);
    scan2_kernel<<<1, SCAN_B>>>();
    scan3_kernel<<<SCAN_B, SCAN_T>>>(N, E);
    fill_kernel<<<(E / 4 + 255) / 256, 256>>>(ei32, E);
    agg_kernel<<<(N * 32 + 255) / 256, 256>>>(N);
    gemm_fp16_kernel<<<(N + 127) / 128, 256>>>(bl, out, N);
}